// round 10
// baseline (speedup 1.0000x reference)
#include <cuda_runtime.h>
#include <math.h>
#include <stdint.h>

#define B_ 4
#define T_ 2048
#define C_ 2048
#define H_ 16
#define D_ 128
#define BT_ (B_*T_)
#define EPS_ 1e-6f

// ---------------- scratch (static device allocations; no cudaMalloc) ----------------
__device__ float d_qkv[(size_t)BT_ * 3 * C_];          // [BT, 3C]
__device__ float d_Qh[(size_t)B_ * H_ * T_ * D_];      // [B,H,T,D]
__device__ float d_Kh[(size_t)B_ * H_ * T_ * D_];
__device__ float d_Vh[(size_t)B_ * H_ * T_ * D_];
__device__ float d_Yb[(size_t)BT_ * C_];               // [BT, C]

// ============================================================================
// common tf32 helpers
// ============================================================================
__device__ __forceinline__ void cp16(uint32_t saddr, const void* g) {
    asm volatile("cp.async.cg.shared.global [%0], [%1], 16;\n" :: "r"(saddr), "l"(g));
}
__device__ __forceinline__ void cp_commit() {
    asm volatile("cp.async.commit_group;\n" ::: "memory");
}
__device__ __forceinline__ void cp_wait1() {
    asm volatile("cp.async.wait_group 1;\n" ::: "memory");
}
__device__ __forceinline__ void cp_wait0() {
    asm volatile("cp.async.wait_group 0;\n" ::: "memory");
}
__device__ __forceinline__ void split_tf32(float x, uint32_t& hi, uint32_t& lo) {
    asm("cvt.rna.tf32.f32 %0, %1;" : "=r"(hi) : "f"(x));
    float r = x - __uint_as_float(hi);
    asm("cvt.rna.tf32.f32 %0, %1;" : "=r"(lo) : "f"(r));
}
__device__ __forceinline__ void mma16n8k8(float* c, const uint32_t* a, const uint32_t* b) {
    asm volatile(
        "mma.sync.aligned.m16n8k8.row.col.f32.tf32.tf32.f32 "
        "{%0,%1,%2,%3}, {%4,%5,%6,%7}, {%8,%9}, {%0,%1,%2,%3};"
        : "+f"(c[0]), "+f"(c[1]), "+f"(c[2]), "+f"(c[3])
        : "r"(a[0]), "r"(a[1]), "r"(a[2]), "r"(a[3]), "r"(b[0]), "r"(b[1]));
}

// ============================================================================
// TF32 tensor-core GEMM with 3xTF32 compensation. (unchanged from R2)
// C[m,n] = sum_k A[m,k] * B[n,k]
// ============================================================================
#define GPAD 36
#define GSTAGE (128 * GPAD)
#define GEMM_SMEM (4 * GSTAGE * 4)

__global__ __launch_bounds__(256, 2)
void gemm_tf32(const float* __restrict__ A, const float* __restrict__ Bm,
               float* __restrict__ C, int M, int N, int K) {
    extern __shared__ float sm[];
    float* As = sm;
    float* Bs = sm + 2 * GSTAGE;

    const int bm = blockIdx.y * 128;
    const int bn = blockIdx.x * 128;
    const int tid = threadIdx.x;
    const int lane = tid & 31;
    const int wid = tid >> 5;
    const int wm = wid >> 2, wn = wid & 3;
    const int m0 = wm * 64, n0 = wn * 32;
    const int g = lane >> 2, t = lane & 3;

    uint32_t as_u = (uint32_t)__cvta_generic_to_shared(As);
    uint32_t bs_u = (uint32_t)__cvta_generic_to_shared(Bs);

    const int NT = K >> 5;

    float acc[4][4][4];
#pragma unroll
    for (int mt = 0; mt < 4; mt++)
#pragma unroll
        for (int nt = 0; nt < 4; nt++)
#pragma unroll
            for (int e = 0; e < 4; e++) acc[mt][nt][e] = 0.f;

    auto issue = [&](int stage, int kt) {
        int kb = kt << 5;
#pragma unroll
        for (int i = 0; i < 4; i++) {
            int idx = tid + i * 256;
            int row = idx >> 3, c = (idx & 7) << 2;
            cp16(as_u + (uint32_t)((stage * 128 + row) * GPAD + c) * 4,
                 A + (size_t)(bm + row) * K + kb + c);
            cp16(bs_u + (uint32_t)((stage * 128 + row) * GPAD + c) * 4,
                 Bm + (size_t)(bn + row) * K + kb + c);
        }
        cp_commit();
    };

    issue(0, 0);

    int buf = 0;
    for (int kt = 0; kt < NT; kt++) {
        if (kt + 1 < NT) { issue(buf ^ 1, kt + 1); cp_wait1(); }
        else            { cp_wait0(); }
        __syncthreads();

        const float* Ab = As + buf * GSTAGE;
        const float* Bb = Bs + buf * GSTAGE;

#pragma unroll
        for (int kk = 0; kk < 4; kk++) {
            const int k = kk << 3;
            uint32_t bh[4][2], bl[4][2];
#pragma unroll
            for (int nt = 0; nt < 4; nt++) {
                const float* bp = Bb + (n0 + nt * 8 + g) * GPAD + k + t;
                split_tf32(bp[0], bh[nt][0], bl[nt][0]);
                split_tf32(bp[4], bh[nt][1], bl[nt][1]);
            }
#pragma unroll
            for (int mt = 0; mt < 4; mt++) {
                const float* ap = Ab + (m0 + mt * 16 + g) * GPAD + k + t;
                uint32_t ah[4], al[4];
                split_tf32(ap[0],            ah[0], al[0]);
                split_tf32(ap[8 * GPAD],     ah[1], al[1]);
                split_tf32(ap[4],            ah[2], al[2]);
                split_tf32(ap[8 * GPAD + 4], ah[3], al[3]);
#pragma unroll
                for (int nt = 0; nt < 4; nt++) {
                    mma16n8k8(acc[mt][nt], ah, bh[nt]);
                    mma16n8k8(acc[mt][nt], ah, bl[nt]);
                    mma16n8k8(acc[mt][nt], al, bh[nt]);
                }
            }
        }
        __syncthreads();
        buf ^= 1;
    }

#pragma unroll
    for (int mt = 0; mt < 4; mt++) {
#pragma unroll
        for (int nt = 0; nt < 4; nt++) {
            int row = bm + m0 + mt * 16 + g;
            int col = bn + n0 + nt * 8 + t * 2;
            *(float2*)&C[(size_t)row * N + col] =
                make_float2(acc[mt][nt][0], acc[mt][nt][1]);
            *(float2*)&C[(size_t)(row + 8) * N + col] =
                make_float2(acc[mt][nt][2], acc[mt][nt][3]);
        }
    }
}

// ============================================================================
// Fused per-head RMSNorm + RoPE + transpose to [B,H,T,D]. (unchanged)
// ============================================================================
__global__ __launch_bounds__(128)
void norm_rope(const float* __restrict__ qkv,
               const float* __restrict__ cosb, const float* __restrict__ sinb,
               const float* __restrict__ gq, const float* __restrict__ gk,
               float* __restrict__ Q, float* __restrict__ K, float* __restrict__ V) {
    const int nh = blockIdx.x;
    const int h = nh % H_;
    const int n = nh / H_;
    const int t = n % T_;
    const int b = n / T_;
    const int d = threadIdx.x;

    const float* base = qkv + (size_t)n * (3 * C_) + h * D_;
    float qv = base[d];
    float kv = base[C_ + d];
    float vv = base[2 * C_ + d];

    __shared__ float redq[4], redk[4];
    __shared__ float qs[D_], ks[D_];

    float sq = qv * qv, sk = kv * kv;
#pragma unroll
    for (int o = 16; o > 0; o >>= 1) {
        sq += __shfl_xor_sync(0xffffffffu, sq, o);
        sk += __shfl_xor_sync(0xffffffffu, sk, o);
    }
    if ((d & 31) == 0) { redq[d >> 5] = sq; redk[d >> 5] = sk; }
    __syncthreads();
    float sumq = redq[0] + redq[1] + redq[2] + redq[3];
    float sumk = redk[0] + redk[1] + redk[2] + redk[3];
    float rq = rsqrtf(sumq * (1.0f / D_) + EPS_);
    float rk = rsqrtf(sumk * (1.0f / D_) + EPS_);

    float qn = qv * rq * gq[d];
    float kn = kv * rk * gk[d];
    qs[d] = qn; ks[d] = kn;
    __syncthreads();

    float qrot = (d < D_ / 2) ? -qs[d + D_ / 2] : qs[d - D_ / 2];
    float krot = (d < D_ / 2) ? -ks[d + D_ / 2] : ks[d - D_ / 2];
    float cv = cosb[(size_t)t * D_ + d];
    float sv = sinb[(size_t)t * D_ + d];

    size_t oidx = (((size_t)(b * H_ + h)) * T_ + t) * D_ + d;
    Q[oidx] = qn * cv + qrot * sv;
    K[oidx] = kn * cv + krot * sv;
    V[oidx] = vv;
}

// ============================================================================
// Flash attention on tensor cores (tf32 3-pass, fp32 accum, online softmax).
// Br=Bc=64, D=128. 128 threads = 4 warps; warp w owns Q rows [w*16, w*16+16).
// Q/K/V fp32 in swizzled smem; P staged through swizzled smem.
// ============================================================================
#define SWK(r,c) (((r) << 7) + ((c) ^ (((r) & 7) << 2)))   // 64x128 arrays
#define SWP(r,c) (((r) << 6) + ((c) ^ (((r) & 7) << 2)))   // 64x64 array
#define FA_SMEM ((3 * 64 * 128 + 64 * 64) * 4)             // 114688 B

__global__ __launch_bounds__(128)
void flash_attn_tc(const float* __restrict__ Q, const float* __restrict__ K,
                   const float* __restrict__ V, float* __restrict__ Y) {
    extern __shared__ float sm[];
    float* Qs = sm;                    // [64][128] swizzled
    float* Ks = Qs + 64 * 128;
    float* Vs = Ks + 64 * 128;
    float* Ps = Vs + 64 * 128;         // [64][64] swizzled

    const int qt = blockIdx.x, h = blockIdx.y, b = blockIdx.z;
    const int tid = threadIdx.x;
    const int lane = tid & 31, w = tid >> 5;
    const int g = lane >> 2, t = lane & 3;
    const int m0 = w * 16;
    const float scale = 0.08838834764831845f; // 1/sqrt(128)

    const size_t headoff = ((size_t)(b * H_ + h)) * T_ * D_;
    const float* Qg = Q + headoff + (size_t)qt * 64 * D_;

    // load Q tile (each warp: one 128-float row per iter, coalesced)
#pragma unroll
    for (int i = 0; i < 16; i++) {
        int idx = tid + (i << 7);
        int r = idx >> 5, c4 = (idx & 31) << 2;
        *(float4*)&Qs[SWK(r, c4)] = *(const float4*)&Qg[(size_t)r * D_ + c4];
    }

    float o[16][4];
#pragma unroll
    for (int n = 0; n < 16; n++)
#pragma unroll
        for (int e = 0; e < 4; e++) o[n][e] = 0.f;
    float mrow0 = -1e30f, mrow1 = -1e30f;
    float lrow0 = 0.f, lrow1 = 0.f;

    for (int kt = 0; kt < T_ / 64; kt++) {
        __syncthreads();   // previous iteration done with Ks/Vs
        const float* Kg = K + headoff + (size_t)kt * 64 * D_;
        const float* Vg = V + headoff + (size_t)kt * 64 * D_;
#pragma unroll
        for (int i = 0; i < 16; i++) {
            int idx = tid + (i << 7);
            int r = idx >> 5, c4 = (idx & 31) << 2;
            *(float4*)&Ks[SWK(r, c4)] = *(const float4*)&Kg[(size_t)r * D_ + c4];
            *(float4*)&Vs[SWK(r, c4)] = *(const float4*)&Vg[(size_t)r * D_ + c4];
        }
        __syncthreads();

        // ---- S = Q K^T (warp: 16x64), tf32 3-pass ----
        float s[8][4];
#pragma unroll
        for (int n = 0; n < 8; n++)
#pragma unroll
            for (int e = 0; e < 4; e++) s[n][e] = 0.f;

#pragma unroll
        for (int k = 0; k < 16; k++) {
            const int kc = k << 3;
            uint32_t ah[4], al[4];
            split_tf32(Qs[SWK(m0 + g,     kc + t)],     ah[0], al[0]);
            split_tf32(Qs[SWK(m0 + g + 8, kc + t)],     ah[1], al[1]);
            split_tf32(Qs[SWK(m0 + g,     kc + t + 4)], ah[2], al[2]);
            split_tf32(Qs[SWK(m0 + g + 8, kc + t + 4)], ah[3], al[3]);
#pragma unroll
            for (int n = 0; n < 8; n++) {
                uint32_t bh[2], bl[2];
                split_tf32(Ks[SWK(n * 8 + g, kc + t)],     bh[0], bl[0]);
                split_tf32(Ks[SWK(n * 8 + g, kc + t + 4)], bh[1], bl[1]);
                mma16n8k8(s[n], ah, bh);
                mma16n8k8(s[n], ah, bl);
                mma16n8k8(s[n], al, bh);
            }
        }

        // ---- online softmax (rows g and g+8 of this warp's 16) ----
        float mx0 = -1e30f, mx1 = -1e30f;
#pragma unroll
        for (int n = 0; n < 8; n++) {
#pragma unroll
            for (int e = 0; e < 4; e++) s[n][e] *= scale;
            mx0 = fmaxf(mx0, fmaxf(s[n][0], s[n][1]));
            mx1 = fmaxf(mx1, fmaxf(s[n][2], s[n][3]));
        }
        mx0 = fmaxf(mx0, __shfl_xor_sync(0xffffffffu, mx0, 1));
        mx0 = fmaxf(mx0, __shfl_xor_sync(0xffffffffu, mx0, 2));
        mx1 = fmaxf(mx1, __shfl_xor_sync(0xffffffffu, mx1, 1));
        mx1 = fmaxf(mx1, __shfl_xor_sync(0xffffffffu, mx1, 2));

        float mn0 = fmaxf(mrow0, mx0);
        float mn1 = fmaxf(mrow1, mx1);
        float corr0 = __expf(mrow0 - mn0);
        float corr1 = __expf(mrow1 - mn1);
        float sum0 = 0.f, sum1 = 0.f;
#pragma unroll
        for (int n = 0; n < 8; n++) {
            float p0 = __expf(s[n][0] - mn0);
            float p1 = __expf(s[n][1] - mn0);
            float p2 = __expf(s[n][2] - mn1);
            float p3 = __expf(s[n][3] - mn1);
            sum0 += p0 + p1;
            sum1 += p2 + p3;
            *(float2*)&Ps[SWP(m0 + g,     n * 8 + 2 * t)] = make_float2(p0, p1);
            *(float2*)&Ps[SWP(m0 + g + 8, n * 8 + 2 * t)] = make_float2(p2, p3);
        }
        sum0 += __shfl_xor_sync(0xffffffffu, sum0, 1);
        sum0 += __shfl_xor_sync(0xffffffffu, sum0, 2);
        sum1 += __shfl_xor_sync(0xffffffffu, sum1, 1);
        sum1 += __shfl_xor_sync(0xffffffffu, sum1, 2);
        lrow0 = lrow0 * corr0 + sum0;
        lrow1 = lrow1 * corr1 + sum1;
        mrow0 = mn0;
        mrow1 = mn1;

#pragma unroll
        for (int n = 0; n < 16; n++) {
            o[n][0] *= corr0; o[n][1] *= corr0;
            o[n][2] *= corr1; o[n][3] *= corr1;
        }
        __syncwarp();

        // ---- O += P V (warp: 16x128 over k=64), tf32 3-pass ----
#pragma unroll
        for (int k = 0; k < 8; k++) {
            const int kc = k << 3;
            uint32_t ah[4], al[4];
            split_tf32(Ps[SWP(m0 + g,     kc + t)],     ah[0], al[0]);
            split_tf32(Ps[SWP(m0 + g + 8, kc + t)],     ah[1], al[1]);
            split_tf32(Ps[SWP(m0 + g,     kc + t + 4)], ah[2], al[2]);
            split_tf32(Ps[SWP(m0 + g + 8, kc + t + 4)], ah[3], al[3]);
#pragma unroll
            for (int n = 0; n < 16; n++) {
                uint32_t bh[2], bl[2];
                // B[d = 8n+g][j = kc+t(+4)] = Vs[j][d]
                split_tf32(Vs[SWK(kc + t,     n * 8 + g)], bh[0], bl[0]);
                split_tf32(Vs[SWK(kc + t + 4, n * 8 + g)], bh[1], bl[1]);
                mma16n8k8(o[n], ah, bh);
                mma16n8k8(o[n], ah, bl);
                mma16n8k8(o[n], al, bh);
            }
        }
    }

    // ---- epilogue: Y[b][t][h*D + d], de-transposed ----
    float inv0 = 1.0f / lrow0;
    float inv1 = 1.0f / lrow1;
    const int r0 = qt * 64 + m0 + g;
    const int r1 = r0 + 8;
#pragma unroll
    for (int n = 0; n < 16; n++) {
        int col = h * D_ + n * 8 + 2 * t;
        *(float2*)&Y[((size_t)b * T_ + r0) * C_ + col] =
            make_float2(o[n][0] * inv0, o[n][1] * inv0);
        *(float2*)&Y[((size_t)b * T_ + r1) * C_ + col] =
            make_float2(o[n][2] * inv1, o[n][3] * inv1);
    }
}

// ============================================================================
extern "C" void kernel_launch(void* const* d_in, const int* in_sizes, int n_in,
                              void* d_out, int out_size) {
    const float* x      = (const float*)d_in[0];  // [B,T,C]
    const float* cosb   = (const float*)d_in[1];  // [T,D]
    const float* sinb   = (const float*)d_in[2];  // [T,D]
    const float* w_qkv  = (const float*)d_in[3];  // [3C,C]
    const float* w_proj = (const float*)d_in[4];  // [C,C]
    const float* gq     = (const float*)d_in[5];  // [D]
    const float* gk     = (const float*)d_in[6];  // [D]
    float* out = (float*)d_out;                   // [B,T,C]

    float *qkv, *Qh, *Kh, *Vh, *Yb;
    cudaGetSymbolAddress((void**)&qkv, d_qkv);
    cudaGetSymbolAddress((void**)&Qh, d_Qh);
    cudaGetSymbolAddress((void**)&Kh, d_Kh);
    cudaGetSymbolAddress((void**)&Vh, d_Vh);
    cudaGetSymbolAddress((void**)&Yb, d_Yb);

    cudaFuncSetAttribute(gemm_tf32, cudaFuncAttributeMaxDynamicSharedMemorySize, GEMM_SMEM);
    cudaFuncSetAttribute(flash_attn_tc, cudaFuncAttributeMaxDynamicSharedMemorySize, FA_SMEM);

    // 1) qkv = x @ w_qkv^T : [8192, 6144]
    gemm_tf32<<<dim3(3 * C_ / 128, BT_ / 128), 256, GEMM_SMEM>>>(x, w_qkv, qkv, BT_, 3 * C_, C_);

    // 2) RMSNorm + RoPE + transpose
    norm_rope<<<BT_ * H_, 128>>>(qkv, cosb, sinb, gq, gk, Qh, Kh, Vh);

    // 3) attention (tensor cores)
    flash_attn_tc<<<dim3(T_ / 64, H_, B_), 128, FA_SMEM>>>(Qh, Kh, Vh, Yb);

    // 4) out = y @ w_proj^T : [8192, 2048]
    gemm_tf32<<<dim3(C_ / 128, BT_ / 128), 256, GEMM_SMEM>>>(Yb, w_proj, out, BT_, C_, C_);
}

// round 11
// speedup vs baseline: 1.0030x; 1.0030x over previous
#include <cuda_runtime.h>
#include <math.h>
#include <stdint.h>

#define B_ 4
#define T_ 2048
#define C_ 2048
#define H_ 16
#define D_ 128
#define BT_ (B_*T_)
#define EPS_ 1e-6f

// ---------------- scratch (static device allocations; no cudaMalloc) ----------------
__device__ float d_qkv[(size_t)BT_ * 3 * C_];          // [BT, 3C]
__device__ float d_Qh[(size_t)B_ * H_ * T_ * D_];      // [B,H,T,D]
__device__ float d_Kh[(size_t)B_ * H_ * T_ * D_];
__device__ float d_Vh[(size_t)B_ * H_ * T_ * D_];
__device__ float d_Yb[(size_t)BT_ * C_];               // [BT, C]

// ============================================================================
// common tf32 helpers
// ============================================================================
__device__ __forceinline__ void cp16(uint32_t saddr, const void* g) {
    asm volatile("cp.async.cg.shared.global [%0], [%1], 16;\n" :: "r"(saddr), "l"(g));
}
__device__ __forceinline__ void cp_commit() {
    asm volatile("cp.async.commit_group;\n" ::: "memory");
}
__device__ __forceinline__ void cp_wait1() {
    asm volatile("cp.async.wait_group 1;\n" ::: "memory");
}
__device__ __forceinline__ void cp_wait0() {
    asm volatile("cp.async.wait_group 0;\n" ::: "memory");
}
__device__ __forceinline__ void split_tf32(float x, uint32_t& hi, uint32_t& lo) {
    asm("cvt.rna.tf32.f32 %0, %1;" : "=r"(hi) : "f"(x));
    float r = x - __uint_as_float(hi);
    asm("cvt.rna.tf32.f32 %0, %1;" : "=r"(lo) : "f"(r));
}
__device__ __forceinline__ void mma16n8k8(float* c, const uint32_t* a, const uint32_t* b) {
    asm volatile(
        "mma.sync.aligned.m16n8k8.row.col.f32.tf32.tf32.f32 "
        "{%0,%1,%2,%3}, {%4,%5,%6,%7}, {%8,%9}, {%0,%1,%2,%3};"
        : "+f"(c[0]), "+f"(c[1]), "+f"(c[2]), "+f"(c[3])
        : "r"(a[0]), "r"(a[1]), "r"(a[2]), "r"(a[3]), "r"(b[0]), "r"(b[1]));
}

// ============================================================================
// TF32 tensor-core GEMM with 3xTF32 compensation. (unchanged from R2)
// C[m,n] = sum_k A[m,k] * B[n,k]
// ============================================================================
#define GPAD 36
#define GSTAGE (128 * GPAD)
#define GEMM_SMEM (4 * GSTAGE * 4)

__global__ __launch_bounds__(256, 2)
void gemm_tf32(const float* __restrict__ A, const float* __restrict__ Bm,
               float* __restrict__ C, int M, int N, int K) {
    extern __shared__ float sm[];
    float* As = sm;
    float* Bs = sm + 2 * GSTAGE;

    const int bm = blockIdx.y * 128;
    const int bn = blockIdx.x * 128;
    const int tid = threadIdx.x;
    const int lane = tid & 31;
    const int wid = tid >> 5;
    const int wm = wid >> 2, wn = wid & 3;
    const int m0 = wm * 64, n0 = wn * 32;
    const int g = lane >> 2, t = lane & 3;

    uint32_t as_u = (uint32_t)__cvta_generic_to_shared(As);
    uint32_t bs_u = (uint32_t)__cvta_generic_to_shared(Bs);

    const int NT = K >> 5;

    float acc[4][4][4];
#pragma unroll
    for (int mt = 0; mt < 4; mt++)
#pragma unroll
        for (int nt = 0; nt < 4; nt++)
#pragma unroll
            for (int e = 0; e < 4; e++) acc[mt][nt][e] = 0.f;

    auto issue = [&](int stage, int kt) {
        int kb = kt << 5;
#pragma unroll
        for (int i = 0; i < 4; i++) {
            int idx = tid + i * 256;
            int row = idx >> 3, c = (idx & 7) << 2;
            cp16(as_u + (uint32_t)((stage * 128 + row) * GPAD + c) * 4,
                 A + (size_t)(bm + row) * K + kb + c);
            cp16(bs_u + (uint32_t)((stage * 128 + row) * GPAD + c) * 4,
                 Bm + (size_t)(bn + row) * K + kb + c);
        }
        cp_commit();
    };

    issue(0, 0);

    int buf = 0;
    for (int kt = 0; kt < NT; kt++) {
        if (kt + 1 < NT) { issue(buf ^ 1, kt + 1); cp_wait1(); }
        else            { cp_wait0(); }
        __syncthreads();

        const float* Ab = As + buf * GSTAGE;
        const float* Bb = Bs + buf * GSTAGE;

#pragma unroll
        for (int kk = 0; kk < 4; kk++) {
            const int k = kk << 3;
            uint32_t bh[4][2], bl[4][2];
#pragma unroll
            for (int nt = 0; nt < 4; nt++) {
                const float* bp = Bb + (n0 + nt * 8 + g) * GPAD + k + t;
                split_tf32(bp[0], bh[nt][0], bl[nt][0]);
                split_tf32(bp[4], bh[nt][1], bl[nt][1]);
            }
#pragma unroll
            for (int mt = 0; mt < 4; mt++) {
                const float* ap = Ab + (m0 + mt * 16 + g) * GPAD + k + t;
                uint32_t ah[4], al[4];
                split_tf32(ap[0],            ah[0], al[0]);
                split_tf32(ap[8 * GPAD],     ah[1], al[1]);
                split_tf32(ap[4],            ah[2], al[2]);
                split_tf32(ap[8 * GPAD + 4], ah[3], al[3]);
#pragma unroll
                for (int nt = 0; nt < 4; nt++) {
                    mma16n8k8(acc[mt][nt], ah, bh[nt]);
                    mma16n8k8(acc[mt][nt], ah, bl[nt]);
                    mma16n8k8(acc[mt][nt], al, bh[nt]);
                }
            }
        }
        __syncthreads();
        buf ^= 1;
    }

#pragma unroll
    for (int mt = 0; mt < 4; mt++) {
#pragma unroll
        for (int nt = 0; nt < 4; nt++) {
            int row = bm + m0 + mt * 16 + g;
            int col = bn + n0 + nt * 8 + t * 2;
            *(float2*)&C[(size_t)row * N + col] =
                make_float2(acc[mt][nt][0], acc[mt][nt][1]);
            *(float2*)&C[(size_t)(row + 8) * N + col] =
                make_float2(acc[mt][nt][2], acc[mt][nt][3]);
        }
    }
}

// ============================================================================
// Fused per-head RMSNorm + RoPE + transpose to [B,H,T,D]. (unchanged)
// ============================================================================
__global__ __launch_bounds__(128)
void norm_rope(const float* __restrict__ qkv,
               const float* __restrict__ cosb, const float* __restrict__ sinb,
               const float* __restrict__ gq, const float* __restrict__ gk,
               float* __restrict__ Q, float* __restrict__ K, float* __restrict__ V) {
    const int nh = blockIdx.x;
    const int h = nh % H_;
    const int n = nh / H_;
    const int t = n % T_;
    const int b = n / T_;
    const int d = threadIdx.x;

    const float* base = qkv + (size_t)n * (3 * C_) + h * D_;
    float qv = base[d];
    float kv = base[C_ + d];
    float vv = base[2 * C_ + d];

    __shared__ float redq[4], redk[4];
    __shared__ float qs[D_], ks[D_];

    float sq = qv * qv, sk = kv * kv;
#pragma unroll
    for (int o = 16; o > 0; o >>= 1) {
        sq += __shfl_xor_sync(0xffffffffu, sq, o);
        sk += __shfl_xor_sync(0xffffffffu, sk, o);
    }
    if ((d & 31) == 0) { redq[d >> 5] = sq; redk[d >> 5] = sk; }
    __syncthreads();
    float sumq = redq[0] + redq[1] + redq[2] + redq[3];
    float sumk = redk[0] + redk[1] + redk[2] + redk[3];
    float rq = rsqrtf(sumq * (1.0f / D_) + EPS_);
    float rk = rsqrtf(sumk * (1.0f / D_) + EPS_);

    float qn = qv * rq * gq[d];
    float kn = kv * rk * gk[d];
    qs[d] = qn; ks[d] = kn;
    __syncthreads();

    float qrot = (d < D_ / 2) ? -qs[d + D_ / 2] : qs[d - D_ / 2];
    float krot = (d < D_ / 2) ? -ks[d + D_ / 2] : ks[d - D_ / 2];
    float cv = cosb[(size_t)t * D_ + d];
    float sv = sinb[(size_t)t * D_ + d];

    size_t oidx = (((size_t)(b * H_ + h)) * T_ + t) * D_ + d;
    Q[oidx] = qn * cv + qrot * sv;
    K[oidx] = kn * cv + krot * sv;
    V[oidx] = vv;
}

// ============================================================================
// Flash attention on tensor cores (tf32 3-pass, fp32 accum, online softmax).
// Br=Bc=64, D=128. 128 threads = 4 warps; warp w owns Q rows [w*16, w*16+16).
// Q/K/V fp32 in swizzled smem; P staged through swizzled smem.
// ============================================================================
#define SWK(r,c) (((r) << 7) + ((c) ^ (((r) & 7) << 2)))   // 64x128 arrays
#define SWP(r,c) (((r) << 6) + ((c) ^ (((r) & 7) << 2)))   // 64x64 array
#define FA_SMEM ((3 * 64 * 128 + 64 * 64) * 4)             // 114688 B

__global__ __launch_bounds__(128)
void flash_attn_tc(const float* __restrict__ Q, const float* __restrict__ K,
                   const float* __restrict__ V, float* __restrict__ Y) {
    extern __shared__ float sm[];
    float* Qs = sm;                    // [64][128] swizzled
    float* Ks = Qs + 64 * 128;
    float* Vs = Ks + 64 * 128;
    float* Ps = Vs + 64 * 128;         // [64][64] swizzled

    const int qt = blockIdx.x, h = blockIdx.y, b = blockIdx.z;
    const int tid = threadIdx.x;
    const int lane = tid & 31, w = tid >> 5;
    const int g = lane >> 2, t = lane & 3;
    const int m0 = w * 16;
    const float scale = 0.08838834764831845f; // 1/sqrt(128)

    const size_t headoff = ((size_t)(b * H_ + h)) * T_ * D_;
    const float* Qg = Q + headoff + (size_t)qt * 64 * D_;

    // load Q tile (each warp: one 128-float row per iter, coalesced)
#pragma unroll
    for (int i = 0; i < 16; i++) {
        int idx = tid + (i << 7);
        int r = idx >> 5, c4 = (idx & 31) << 2;
        *(float4*)&Qs[SWK(r, c4)] = *(const float4*)&Qg[(size_t)r * D_ + c4];
    }

    float o[16][4];
#pragma unroll
    for (int n = 0; n < 16; n++)
#pragma unroll
        for (int e = 0; e < 4; e++) o[n][e] = 0.f;
    float mrow0 = -1e30f, mrow1 = -1e30f;
    float lrow0 = 0.f, lrow1 = 0.f;

    for (int kt = 0; kt < T_ / 64; kt++) {
        __syncthreads();   // previous iteration done with Ks/Vs
        const float* Kg = K + headoff + (size_t)kt * 64 * D_;
        const float* Vg = V + headoff + (size_t)kt * 64 * D_;
#pragma unroll
        for (int i = 0; i < 16; i++) {
            int idx = tid + (i << 7);
            int r = idx >> 5, c4 = (idx & 31) << 2;
            *(float4*)&Ks[SWK(r, c4)] = *(const float4*)&Kg[(size_t)r * D_ + c4];
            *(float4*)&Vs[SWK(r, c4)] = *(const float4*)&Vg[(size_t)r * D_ + c4];
        }
        __syncthreads();

        // ---- S = Q K^T (warp: 16x64), tf32 3-pass ----
        float s[8][4];
#pragma unroll
        for (int n = 0; n < 8; n++)
#pragma unroll
            for (int e = 0; e < 4; e++) s[n][e] = 0.f;

#pragma unroll
        for (int k = 0; k < 16; k++) {
            const int kc = k << 3;
            uint32_t ah[4], al[4];
            split_tf32(Qs[SWK(m0 + g,     kc + t)],     ah[0], al[0]);
            split_tf32(Qs[SWK(m0 + g + 8, kc + t)],     ah[1], al[1]);
            split_tf32(Qs[SWK(m0 + g,     kc + t + 4)], ah[2], al[2]);
            split_tf32(Qs[SWK(m0 + g + 8, kc + t + 4)], ah[3], al[3]);
#pragma unroll
            for (int n = 0; n < 8; n++) {
                uint32_t bh[2], bl[2];
                split_tf32(Ks[SWK(n * 8 + g, kc + t)],     bh[0], bl[0]);
                split_tf32(Ks[SWK(n * 8 + g, kc + t + 4)], bh[1], bl[1]);
                mma16n8k8(s[n], ah, bh);
                mma16n8k8(s[n], ah, bl);
                mma16n8k8(s[n], al, bh);
            }
        }

        // ---- online softmax (rows g and g+8 of this warp's 16) ----
        float mx0 = -1e30f, mx1 = -1e30f;
#pragma unroll
        for (int n = 0; n < 8; n++) {
#pragma unroll
            for (int e = 0; e < 4; e++) s[n][e] *= scale;
            mx0 = fmaxf(mx0, fmaxf(s[n][0], s[n][1]));
            mx1 = fmaxf(mx1, fmaxf(s[n][2], s[n][3]));
        }
        mx0 = fmaxf(mx0, __shfl_xor_sync(0xffffffffu, mx0, 1));
        mx0 = fmaxf(mx0, __shfl_xor_sync(0xffffffffu, mx0, 2));
        mx1 = fmaxf(mx1, __shfl_xor_sync(0xffffffffu, mx1, 1));
        mx1 = fmaxf(mx1, __shfl_xor_sync(0xffffffffu, mx1, 2));

        float mn0 = fmaxf(mrow0, mx0);
        float mn1 = fmaxf(mrow1, mx1);
        float corr0 = __expf(mrow0 - mn0);
        float corr1 = __expf(mrow1 - mn1);
        float sum0 = 0.f, sum1 = 0.f;
#pragma unroll
        for (int n = 0; n < 8; n++) {
            float p0 = __expf(s[n][0] - mn0);
            float p1 = __expf(s[n][1] - mn0);
            float p2 = __expf(s[n][2] - mn1);
            float p3 = __expf(s[n][3] - mn1);
            sum0 += p0 + p1;
            sum1 += p2 + p3;
            *(float2*)&Ps[SWP(m0 + g,     n * 8 + 2 * t)] = make_float2(p0, p1);
            *(float2*)&Ps[SWP(m0 + g + 8, n * 8 + 2 * t)] = make_float2(p2, p3);
        }
        sum0 += __shfl_xor_sync(0xffffffffu, sum0, 1);
        sum0 += __shfl_xor_sync(0xffffffffu, sum0, 2);
        sum1 += __shfl_xor_sync(0xffffffffu, sum1, 1);
        sum1 += __shfl_xor_sync(0xffffffffu, sum1, 2);
        lrow0 = lrow0 * corr0 + sum0;
        lrow1 = lrow1 * corr1 + sum1;
        mrow0 = mn0;
        mrow1 = mn1;

#pragma unroll
        for (int n = 0; n < 16; n++) {
            o[n][0] *= corr0; o[n][1] *= corr0;
            o[n][2] *= corr1; o[n][3] *= corr1;
        }
        __syncwarp();

        // ---- O += P V (warp: 16x128 over k=64), tf32 3-pass ----
#pragma unroll
        for (int k = 0; k < 8; k++) {
            const int kc = k << 3;
            uint32_t ah[4], al[4];
            split_tf32(Ps[SWP(m0 + g,     kc + t)],     ah[0], al[0]);
            split_tf32(Ps[SWP(m0 + g + 8, kc + t)],     ah[1], al[1]);
            split_tf32(Ps[SWP(m0 + g,     kc + t + 4)], ah[2], al[2]);
            split_tf32(Ps[SWP(m0 + g + 8, kc + t + 4)], ah[3], al[3]);
#pragma unroll
            for (int n = 0; n < 16; n++) {
                uint32_t bh[2], bl[2];
                // B[d = 8n+g][j = kc+t(+4)] = Vs[j][d]
                split_tf32(Vs[SWK(kc + t,     n * 8 + g)], bh[0], bl[0]);
                split_tf32(Vs[SWK(kc + t + 4, n * 8 + g)], bh[1], bl[1]);
                mma16n8k8(o[n], ah, bh);
                mma16n8k8(o[n], ah, bl);
                mma16n8k8(o[n], al, bh);
            }
        }
    }

    // ---- epilogue: Y[b][t][h*D + d], de-transposed ----
    float inv0 = 1.0f / lrow0;
    float inv1 = 1.0f / lrow1;
    const int r0 = qt * 64 + m0 + g;
    const int r1 = r0 + 8;
#pragma unroll
    for (int n = 0; n < 16; n++) {
        int col = h * D_ + n * 8 + 2 * t;
        *(float2*)&Y[((size_t)b * T_ + r0) * C_ + col] =
            make_float2(o[n][0] * inv0, o[n][1] * inv0);
        *(float2*)&Y[((size_t)b * T_ + r1) * C_ + col] =
            make_float2(o[n][2] * inv1, o[n][3] * inv1);
    }
}

// ============================================================================
extern "C" void kernel_launch(void* const* d_in, const int* in_sizes, int n_in,
                              void* d_out, int out_size) {
    const float* x      = (const float*)d_in[0];  // [B,T,C]
    const float* cosb   = (const float*)d_in[1];  // [T,D]
    const float* sinb   = (const float*)d_in[2];  // [T,D]
    const float* w_qkv  = (const float*)d_in[3];  // [3C,C]
    const float* w_proj = (const float*)d_in[4];  // [C,C]
    const float* gq     = (const float*)d_in[5];  // [D]
    const float* gk     = (const float*)d_in[6];  // [D]
    float* out = (float*)d_out;                   // [B,T,C]

    float *qkv, *Qh, *Kh, *Vh, *Yb;
    cudaGetSymbolAddress((void**)&qkv, d_qkv);
    cudaGetSymbolAddress((void**)&Qh, d_Qh);
    cudaGetSymbolAddress((void**)&Kh, d_Kh);
    cudaGetSymbolAddress((void**)&Vh, d_Vh);
    cudaGetSymbolAddress((void**)&Yb, d_Yb);

    cudaFuncSetAttribute(gemm_tf32, cudaFuncAttributeMaxDynamicSharedMemorySize, GEMM_SMEM);
    cudaFuncSetAttribute(flash_attn_tc, cudaFuncAttributeMaxDynamicSharedMemorySize, FA_SMEM);

    // 1) qkv = x @ w_qkv^T : [8192, 6144]
    gemm_tf32<<<dim3(3 * C_ / 128, BT_ / 128), 256, GEMM_SMEM>>>(x, w_qkv, qkv, BT_, 3 * C_, C_);

    // 2) RMSNorm + RoPE + transpose
    norm_rope<<<BT_ * H_, 128>>>(qkv, cosb, sinb, gq, gk, Qh, Kh, Vh);

    // 3) attention (tensor cores)
    flash_attn_tc<<<dim3(T_ / 64, H_, B_), 128, FA_SMEM>>>(Qh, Kh, Vh, Yb);

    // 4) out = y @ w_proj^T : [8192, 2048]
    gemm_tf32<<<dim3(C_ / 128, BT_ / 128), 256, GEMM_SMEM>>>(Yb, w_proj, out, BT_, C_, C_);
}

// round 12
// speedup vs baseline: 1.0058x; 1.0028x over previous
#include <cuda_runtime.h>
#include <math.h>
#include <stdint.h>

#define B_ 4
#define T_ 2048
#define C_ 2048
#define H_ 16
#define D_ 128
#define BT_ (B_*T_)
#define EPS_ 1e-6f

// ---------------- scratch (static device allocations; no cudaMalloc) ----------------
__device__ float d_qkv[(size_t)BT_ * 3 * C_];          // [BT, 3C]
__device__ float d_Qh[(size_t)B_ * H_ * T_ * D_];      // [B,H,T,D]
__device__ float d_Kh[(size_t)B_ * H_ * T_ * D_];
__device__ float d_Vh[(size_t)B_ * H_ * T_ * D_];
__device__ float d_Yb[(size_t)BT_ * C_];               // [BT, C]

// ============================================================================
// common tf32 helpers
// ============================================================================
__device__ __forceinline__ void cp16(uint32_t saddr, const void* g) {
    asm volatile("cp.async.cg.shared.global [%0], [%1], 16;\n" :: "r"(saddr), "l"(g));
}
__device__ __forceinline__ void cp_commit() {
    asm volatile("cp.async.commit_group;\n" ::: "memory");
}
__device__ __forceinline__ void cp_wait1() {
    asm volatile("cp.async.wait_group 1;\n" ::: "memory");
}
__device__ __forceinline__ void cp_wait0() {
    asm volatile("cp.async.wait_group 0;\n" ::: "memory");
}
__device__ __forceinline__ void split_tf32(float x, uint32_t& hi, uint32_t& lo) {
    asm("cvt.rna.tf32.f32 %0, %1;" : "=r"(hi) : "f"(x));
    float r = x - __uint_as_float(hi);
    asm("cvt.rna.tf32.f32 %0, %1;" : "=r"(lo) : "f"(r));
}
__device__ __forceinline__ void mma16n8k8(float* c, const uint32_t* a, const uint32_t* b) {
    asm volatile(
        "mma.sync.aligned.m16n8k8.row.col.f32.tf32.tf32.f32 "
        "{%0,%1,%2,%3}, {%4,%5,%6,%7}, {%8,%9}, {%0,%1,%2,%3};"
        : "+f"(c[0]), "+f"(c[1]), "+f"(c[2]), "+f"(c[3])
        : "r"(a[0]), "r"(a[1]), "r"(a[2]), "r"(a[3]), "r"(b[0]), "r"(b[1]));
}

// ============================================================================
// TF32 tensor-core GEMM with 3xTF32 compensation. (unchanged from R2)
// C[m,n] = sum_k A[m,k] * B[n,k]
// ============================================================================
#define GPAD 36
#define GSTAGE (128 * GPAD)
#define GEMM_SMEM (4 * GSTAGE * 4)

__global__ __launch_bounds__(256, 2)
void gemm_tf32(const float* __restrict__ A, const float* __restrict__ Bm,
               float* __restrict__ C, int M, int N, int K) {
    extern __shared__ float sm[];
    float* As = sm;
    float* Bs = sm + 2 * GSTAGE;

    const int bm = blockIdx.y * 128;
    const int bn = blockIdx.x * 128;
    const int tid = threadIdx.x;
    const int lane = tid & 31;
    const int wid = tid >> 5;
    const int wm = wid >> 2, wn = wid & 3;
    const int m0 = wm * 64, n0 = wn * 32;
    const int g = lane >> 2, t = lane & 3;

    uint32_t as_u = (uint32_t)__cvta_generic_to_shared(As);
    uint32_t bs_u = (uint32_t)__cvta_generic_to_shared(Bs);

    const int NT = K >> 5;

    float acc[4][4][4];
#pragma unroll
    for (int mt = 0; mt < 4; mt++)
#pragma unroll
        for (int nt = 0; nt < 4; nt++)
#pragma unroll
            for (int e = 0; e < 4; e++) acc[mt][nt][e] = 0.f;

    auto issue = [&](int stage, int kt) {
        int kb = kt << 5;
#pragma unroll
        for (int i = 0; i < 4; i++) {
            int idx = tid + i * 256;
            int row = idx >> 3, c = (idx & 7) << 2;
            cp16(as_u + (uint32_t)((stage * 128 + row) * GPAD + c) * 4,
                 A + (size_t)(bm + row) * K + kb + c);
            cp16(bs_u + (uint32_t)((stage * 128 + row) * GPAD + c) * 4,
                 Bm + (size_t)(bn + row) * K + kb + c);
        }
        cp_commit();
    };

    issue(0, 0);

    int buf = 0;
    for (int kt = 0; kt < NT; kt++) {
        if (kt + 1 < NT) { issue(buf ^ 1, kt + 1); cp_wait1(); }
        else            { cp_wait0(); }
        __syncthreads();

        const float* Ab = As + buf * GSTAGE;
        const float* Bb = Bs + buf * GSTAGE;

#pragma unroll
        for (int kk = 0; kk < 4; kk++) {
            const int k = kk << 3;
            uint32_t bh[4][2], bl[4][2];
#pragma unroll
            for (int nt = 0; nt < 4; nt++) {
                const float* bp = Bb + (n0 + nt * 8 + g) * GPAD + k + t;
                split_tf32(bp[0], bh[nt][0], bl[nt][0]);
                split_tf32(bp[4], bh[nt][1], bl[nt][1]);
            }
#pragma unroll
            for (int mt = 0; mt < 4; mt++) {
                const float* ap = Ab + (m0 + mt * 16 + g) * GPAD + k + t;
                uint32_t ah[4], al[4];
                split_tf32(ap[0],            ah[0], al[0]);
                split_tf32(ap[8 * GPAD],     ah[1], al[1]);
                split_tf32(ap[4],            ah[2], al[2]);
                split_tf32(ap[8 * GPAD + 4], ah[3], al[3]);
#pragma unroll
                for (int nt = 0; nt < 4; nt++) {
                    mma16n8k8(acc[mt][nt], ah, bh[nt]);
                    mma16n8k8(acc[mt][nt], ah, bl[nt]);
                    mma16n8k8(acc[mt][nt], al, bh[nt]);
                }
            }
        }
        __syncthreads();
        buf ^= 1;
    }

#pragma unroll
    for (int mt = 0; mt < 4; mt++) {
#pragma unroll
        for (int nt = 0; nt < 4; nt++) {
            int row = bm + m0 + mt * 16 + g;
            int col = bn + n0 + nt * 8 + t * 2;
            *(float2*)&C[(size_t)row * N + col] =
                make_float2(acc[mt][nt][0], acc[mt][nt][1]);
            *(float2*)&C[(size_t)(row + 8) * N + col] =
                make_float2(acc[mt][nt][2], acc[mt][nt][3]);
        }
    }
}

// ============================================================================
// Fused per-head RMSNorm + RoPE + transpose to [B,H,T,D]. (unchanged)
// ============================================================================
__global__ __launch_bounds__(128)
void norm_rope(const float* __restrict__ qkv,
               const float* __restrict__ cosb, const float* __restrict__ sinb,
               const float* __restrict__ gq, const float* __restrict__ gk,
               float* __restrict__ Q, float* __restrict__ K, float* __restrict__ V) {
    const int nh = blockIdx.x;
    const int h = nh % H_;
    const int n = nh / H_;
    const int t = n % T_;
    const int b = n / T_;
    const int d = threadIdx.x;

    const float* base = qkv + (size_t)n * (3 * C_) + h * D_;
    float qv = base[d];
    float kv = base[C_ + d];
    float vv = base[2 * C_ + d];

    __shared__ float redq[4], redk[4];
    __shared__ float qs[D_], ks[D_];

    float sq = qv * qv, sk = kv * kv;
#pragma unroll
    for (int o = 16; o > 0; o >>= 1) {
        sq += __shfl_xor_sync(0xffffffffu, sq, o);
        sk += __shfl_xor_sync(0xffffffffu, sk, o);
    }
    if ((d & 31) == 0) { redq[d >> 5] = sq; redk[d >> 5] = sk; }
    __syncthreads();
    float sumq = redq[0] + redq[1] + redq[2] + redq[3];
    float sumk = redk[0] + redk[1] + redk[2] + redk[3];
    float rq = rsqrtf(sumq * (1.0f / D_) + EPS_);
    float rk = rsqrtf(sumk * (1.0f / D_) + EPS_);

    float qn = qv * rq * gq[d];
    float kn = kv * rk * gk[d];
    qs[d] = qn; ks[d] = kn;
    __syncthreads();

    float qrot = (d < D_ / 2) ? -qs[d + D_ / 2] : qs[d - D_ / 2];
    float krot = (d < D_ / 2) ? -ks[d + D_ / 2] : ks[d - D_ / 2];
    float cv = cosb[(size_t)t * D_ + d];
    float sv = sinb[(size_t)t * D_ + d];

    size_t oidx = (((size_t)(b * H_ + h)) * T_ + t) * D_ + d;
    Q[oidx] = qn * cv + qrot * sv;
    K[oidx] = kn * cv + krot * sv;
    V[oidx] = vv;
}

// ============================================================================
// Flash attention on tensor cores (tf32 3-pass, fp32 accum, online softmax).
// Br=Bc=64, D=128. 128 threads = 4 warps; warp w owns Q rows [w*16, w*16+16).
// Q/K/V fp32 in swizzled smem; P staged through swizzled smem.
// ============================================================================
#define SWK(r,c) (((r) << 7) + ((c) ^ (((r) & 7) << 2)))   // 64x128 arrays
#define SWP(r,c) (((r) << 6) + ((c) ^ (((r) & 7) << 2)))   // 64x64 array
#define FA_SMEM ((3 * 64 * 128 + 64 * 64) * 4)             // 114688 B

__global__ __launch_bounds__(128)
void flash_attn_tc(const float* __restrict__ Q, const float* __restrict__ K,
                   const float* __restrict__ V, float* __restrict__ Y) {
    extern __shared__ float sm[];
    float* Qs = sm;                    // [64][128] swizzled
    float* Ks = Qs + 64 * 128;
    float* Vs = Ks + 64 * 128;
    float* Ps = Vs + 64 * 128;         // [64][64] swizzled

    const int qt = blockIdx.x, h = blockIdx.y, b = blockIdx.z;
    const int tid = threadIdx.x;
    const int lane = tid & 31, w = tid >> 5;
    const int g = lane >> 2, t = lane & 3;
    const int m0 = w * 16;
    const float scale = 0.08838834764831845f; // 1/sqrt(128)

    const size_t headoff = ((size_t)(b * H_ + h)) * T_ * D_;
    const float* Qg = Q + headoff + (size_t)qt * 64 * D_;

    // load Q tile (each warp: one 128-float row per iter, coalesced)
#pragma unroll
    for (int i = 0; i < 16; i++) {
        int idx = tid + (i << 7);
        int r = idx >> 5, c4 = (idx & 31) << 2;
        *(float4*)&Qs[SWK(r, c4)] = *(const float4*)&Qg[(size_t)r * D_ + c4];
    }

    float o[16][4];
#pragma unroll
    for (int n = 0; n < 16; n++)
#pragma unroll
        for (int e = 0; e < 4; e++) o[n][e] = 0.f;
    float mrow0 = -1e30f, mrow1 = -1e30f;
    float lrow0 = 0.f, lrow1 = 0.f;

    for (int kt = 0; kt < T_ / 64; kt++) {
        __syncthreads();   // previous iteration done with Ks/Vs
        const float* Kg = K + headoff + (size_t)kt * 64 * D_;
        const float* Vg = V + headoff + (size_t)kt * 64 * D_;
#pragma unroll
        for (int i = 0; i < 16; i++) {
            int idx = tid + (i << 7);
            int r = idx >> 5, c4 = (idx & 31) << 2;
            *(float4*)&Ks[SWK(r, c4)] = *(const float4*)&Kg[(size_t)r * D_ + c4];
            *(float4*)&Vs[SWK(r, c4)] = *(const float4*)&Vg[(size_t)r * D_ + c4];
        }
        __syncthreads();

        // ---- S = Q K^T (warp: 16x64), tf32 3-pass ----
        float s[8][4];
#pragma unroll
        for (int n = 0; n < 8; n++)
#pragma unroll
            for (int e = 0; e < 4; e++) s[n][e] = 0.f;

#pragma unroll
        for (int k = 0; k < 16; k++) {
            const int kc = k << 3;
            uint32_t ah[4], al[4];
            split_tf32(Qs[SWK(m0 + g,     kc + t)],     ah[0], al[0]);
            split_tf32(Qs[SWK(m0 + g + 8, kc + t)],     ah[1], al[1]);
            split_tf32(Qs[SWK(m0 + g,     kc + t + 4)], ah[2], al[2]);
            split_tf32(Qs[SWK(m0 + g + 8, kc + t + 4)], ah[3], al[3]);
#pragma unroll
            for (int n = 0; n < 8; n++) {
                uint32_t bh[2], bl[2];
                split_tf32(Ks[SWK(n * 8 + g, kc + t)],     bh[0], bl[0]);
                split_tf32(Ks[SWK(n * 8 + g, kc + t + 4)], bh[1], bl[1]);
                mma16n8k8(s[n], ah, bh);
                mma16n8k8(s[n], ah, bl);
                mma16n8k8(s[n], al, bh);
            }
        }

        // ---- online softmax (rows g and g+8 of this warp's 16) ----
        float mx0 = -1e30f, mx1 = -1e30f;
#pragma unroll
        for (int n = 0; n < 8; n++) {
#pragma unroll
            for (int e = 0; e < 4; e++) s[n][e] *= scale;
            mx0 = fmaxf(mx0, fmaxf(s[n][0], s[n][1]));
            mx1 = fmaxf(mx1, fmaxf(s[n][2], s[n][3]));
        }
        mx0 = fmaxf(mx0, __shfl_xor_sync(0xffffffffu, mx0, 1));
        mx0 = fmaxf(mx0, __shfl_xor_sync(0xffffffffu, mx0, 2));
        mx1 = fmaxf(mx1, __shfl_xor_sync(0xffffffffu, mx1, 1));
        mx1 = fmaxf(mx1, __shfl_xor_sync(0xffffffffu, mx1, 2));

        float mn0 = fmaxf(mrow0, mx0);
        float mn1 = fmaxf(mrow1, mx1);
        float corr0 = __expf(mrow0 - mn0);
        float corr1 = __expf(mrow1 - mn1);
        float sum0 = 0.f, sum1 = 0.f;
#pragma unroll
        for (int n = 0; n < 8; n++) {
            float p0 = __expf(s[n][0] - mn0);
            float p1 = __expf(s[n][1] - mn0);
            float p2 = __expf(s[n][2] - mn1);
            float p3 = __expf(s[n][3] - mn1);
            sum0 += p0 + p1;
            sum1 += p2 + p3;
            *(float2*)&Ps[SWP(m0 + g,     n * 8 + 2 * t)] = make_float2(p0, p1);
            *(float2*)&Ps[SWP(m0 + g + 8, n * 8 + 2 * t)] = make_float2(p2, p3);
        }
        sum0 += __shfl_xor_sync(0xffffffffu, sum0, 1);
        sum0 += __shfl_xor_sync(0xffffffffu, sum0, 2);
        sum1 += __shfl_xor_sync(0xffffffffu, sum1, 1);
        sum1 += __shfl_xor_sync(0xffffffffu, sum1, 2);
        lrow0 = lrow0 * corr0 + sum0;
        lrow1 = lrow1 * corr1 + sum1;
        mrow0 = mn0;
        mrow1 = mn1;

#pragma unroll
        for (int n = 0; n < 16; n++) {
            o[n][0] *= corr0; o[n][1] *= corr0;
            o[n][2] *= corr1; o[n][3] *= corr1;
        }
        __syncwarp();

        // ---- O += P V (warp: 16x128 over k=64), tf32 3-pass ----
#pragma unroll
        for (int k = 0; k < 8; k++) {
            const int kc = k << 3;
            uint32_t ah[4], al[4];
            split_tf32(Ps[SWP(m0 + g,     kc + t)],     ah[0], al[0]);
            split_tf32(Ps[SWP(m0 + g + 8, kc + t)],     ah[1], al[1]);
            split_tf32(Ps[SWP(m0 + g,     kc + t + 4)], ah[2], al[2]);
            split_tf32(Ps[SWP(m0 + g + 8, kc + t + 4)], ah[3], al[3]);
#pragma unroll
            for (int n = 0; n < 16; n++) {
                uint32_t bh[2], bl[2];
                // B[d = 8n+g][j = kc+t(+4)] = Vs[j][d]
                split_tf32(Vs[SWK(kc + t,     n * 8 + g)], bh[0], bl[0]);
                split_tf32(Vs[SWK(kc + t + 4, n * 8 + g)], bh[1], bl[1]);
                mma16n8k8(o[n], ah, bh);
                mma16n8k8(o[n], ah, bl);
                mma16n8k8(o[n], al, bh);
            }
        }
    }

    // ---- epilogue: Y[b][t][h*D + d], de-transposed ----
    float inv0 = 1.0f / lrow0;
    float inv1 = 1.0f / lrow1;
    const int r0 = qt * 64 + m0 + g;
    const int r1 = r0 + 8;
#pragma unroll
    for (int n = 0; n < 16; n++) {
        int col = h * D_ + n * 8 + 2 * t;
        *(float2*)&Y[((size_t)b * T_ + r0) * C_ + col] =
            make_float2(o[n][0] * inv0, o[n][1] * inv0);
        *(float2*)&Y[((size_t)b * T_ + r1) * C_ + col] =
            make_float2(o[n][2] * inv1, o[n][3] * inv1);
    }
}

// ============================================================================
extern "C" void kernel_launch(void* const* d_in, const int* in_sizes, int n_in,
                              void* d_out, int out_size) {
    const float* x      = (const float*)d_in[0];  // [B,T,C]
    const float* cosb   = (const float*)d_in[1];  // [T,D]
    const float* sinb   = (const float*)d_in[2];  // [T,D]
    const float* w_qkv  = (const float*)d_in[3];  // [3C,C]
    const float* w_proj = (const float*)d_in[4];  // [C,C]
    const float* gq     = (const float*)d_in[5];  // [D]
    const float* gk     = (const float*)d_in[6];  // [D]
    float* out = (float*)d_out;                   // [B,T,C]

    float *qkv, *Qh, *Kh, *Vh, *Yb;
    cudaGetSymbolAddress((void**)&qkv, d_qkv);
    cudaGetSymbolAddress((void**)&Qh, d_Qh);
    cudaGetSymbolAddress((void**)&Kh, d_Kh);
    cudaGetSymbolAddress((void**)&Vh, d_Vh);
    cudaGetSymbolAddress((void**)&Yb, d_Yb);

    cudaFuncSetAttribute(gemm_tf32, cudaFuncAttributeMaxDynamicSharedMemorySize, GEMM_SMEM);
    cudaFuncSetAttribute(flash_attn_tc, cudaFuncAttributeMaxDynamicSharedMemorySize, FA_SMEM);

    // 1) qkv = x @ w_qkv^T : [8192, 6144]
    gemm_tf32<<<dim3(3 * C_ / 128, BT_ / 128), 256, GEMM_SMEM>>>(x, w_qkv, qkv, BT_, 3 * C_, C_);

    // 2) RMSNorm + RoPE + transpose
    norm_rope<<<BT_ * H_, 128>>>(qkv, cosb, sinb, gq, gk, Qh, Kh, Vh);

    // 3) attention (tensor cores)
    flash_attn_tc<<<dim3(T_ / 64, H_, B_), 128, FA_SMEM>>>(Qh, Kh, Vh, Yb);

    // 4) out = y @ w_proj^T : [8192, 2048]
    gemm_tf32<<<dim3(C_ / 128, BT_ / 128), 256, GEMM_SMEM>>>(Yb, w_proj, out, BT_, C_, C_);
}